// round 17
// baseline (speedup 1.0000x reference)
#include <cuda_runtime.h>
#include <cuda_fp16.h>
#include <cstdint>

// ---------------- scratch (no allocations allowed) ----------------
__device__ float    g_qkv[(size_t)8 * 768 * 4096];   // fp32
__device__ float    g_agg[(size_t)8 * 768 * 4096];   // fp32
__device__ float    g_kv[8 * 64 * 72];
// interleaved (big, small) packed-half2 pairs: 2 uint32 per element
__device__ uint32_t g_x2[(size_t)2 * 8 * 128 * 4096];    // x    [b][kp][px][2]
__device__ uint32_t g_att2[(size_t)2 * 8 * 256 * 4096];  // att  [b][kp][px][2]
__device__ uint32_t g_wq2[2 * 768 * 128];                // w_qkv  [m][kp][2]
__device__ uint32_t g_wp2[2 * 256 * 256];                // w_proj [m][kp][2]

#define HW 4096
#define NB 8
#define A_SCALE 128.0f
#define B_SCALE 16.0f
#define INV_SC  (1.0f / (A_SCALE * B_SCALE))   // 2^-11

// split scaled pair into packed fp16 big + small
__device__ __forceinline__ void splith(float x, float y, float sc,
                                       uint32_t& pb, uint32_t& ps) {
    float xs = x * sc, ys = y * sc;
    __half hx = __float2half_rn(xs), hy = __float2half_rn(ys);
    float rx = xs - __half2float(hx), ry = ys - __half2float(hy);
    __half sx = __float2half_rn(rx), sy = __float2half_rn(ry);
    __half2 vb = __halves2half2(hx, hy);
    __half2 vs = __halves2half2(sx, sy);
    pb = *reinterpret_cast<uint32_t*>(&vb);
    ps = *reinterpret_cast<uint32_t*>(&vs);
}

#define MMA_F16(C, Ar, Br)                                               \
    asm volatile(                                                        \
        "mma.sync.aligned.m16n8k16.row.col.f32.f16.f16.f32 "             \
        "{%0,%1,%2,%3}, {%4,%5,%6,%7}, {%8,%9}, {%0,%1,%2,%3};"          \
        : "+f"((C)[0]), "+f"((C)[1]), "+f"((C)[2]), "+f"((C)[3])         \
        : "r"((Ar)[0]), "r"((Ar)[1]), "r"((Ar)[2]), "r"((Ar)[3]),        \
          "r"((Br)[0]), "r"((Br)[1]))

#define CP_ASYNC16(smem_addr, gptr)                                      \
    asm volatile("cp.async.cg.shared.global [%0], [%1], 16;"             \
                 :: "r"(smem_addr), "l"(gptr) : "memory")

// ---------------- weight split kernel (tiny) ----------------
__global__ void split_w_kernel(const float* __restrict__ wq,
                               const float* __restrict__ wp)
{
    int idx = blockIdx.x * 256 + threadIdx.x;
    if (idx < 768 * 128) {
        int m = idx >> 7, kp = idx & 127;
        float2 v = *reinterpret_cast<const float2*>(&wq[m * 256 + 2 * kp]);
        uint32_t pb, ps;
        splith(v.x, v.y, A_SCALE, pb, ps);
        reinterpret_cast<uint2*>(g_wq2)[idx] = make_uint2(pb, ps);
    } else {
        int j = idx - 768 * 128;
        if (j < 256 * 256) {
            int m = j >> 8, kp = j & 255;
            float2 v = *reinterpret_cast<const float2*>(&wp[m * 512 + 2 * kp]);
            uint32_t pb, ps;
            splith(v.x, v.y, A_SCALE, pb, ps);
            reinterpret_cast<uint2*>(g_wp2)[j] = make_uint2(pb, ps);
        }
    }
}

// ---------------- x split kernel ----------------
__global__ __launch_bounds__(256)
void split_x_kernel(const float* __restrict__ x)
{
    int idx = blockIdx.x * 256 + threadIdx.x;    // [b][kp][p]
    int p = idx & 4095;
    int rest = idx >> 12;
    int kp = rest & 127;
    int b = rest >> 7;
    const float* xp = x + ((size_t)b * 256 + 2 * kp) * HW + p;
    uint32_t pb, ps;
    splith(xp[0], xp[HW], B_SCALE, pb, ps);
    reinterpret_cast<uint2*>(g_x2)[idx] = make_uint2(pb, ps);
}

// ---------------- fp16 split tensor-core GEMM, interleaved LDS.64 frags ----------------
// A smem: [128 m][40 u32]  (16 kp x (big,small), stride 40 -> bank-safe LDS.64)
// B smem: [16 kp][264 u32] (128 n x (big,small), stride 264 -> bank-safe LDS.64)
#define A_STRIDE 40
#define B_STRIDE 264
#define ST_B (128 * A_STRIDE * 4)            // 20480
#define STAGE (ST_B + 16 * B_STRIDE * 4)     // 37376
#define GEMM_SMEM (3 * STAGE)                // 112128

__global__ __launch_bounds__(256, 2)
void gemm_kernel(const uint32_t* __restrict__ A2,
                 const uint32_t* __restrict__ B2,
                 float* __restrict__ Cdst, int Kp,
                 const float* __restrict__ bn_gamma, const float* __restrict__ bn_beta,
                 const float* __restrict__ bn_mean,  const float* __restrict__ bn_var)
{
    extern __shared__ __align__(16) char smem[];
    uint32_t sbase;
    asm("{ .reg .u64 t; cvta.to.shared.u64 t, %1; cvt.u32.u64 %0, t; }"
        : "=r"(sbase) : "l"(smem));

    const int tid  = threadIdx.x;
    const int lane = tid & 31;
    const int warp = tid >> 5;
    const int warpM = (warp >> 2) * 64;
    const int warpN = (warp & 3) * 32;
    const int lq = lane >> 2;
    const int lr = lane & 3;

    const int b  = blockIdx.z;
    const int m0 = blockIdx.x * 128;
    const int n0 = blockIdx.y * 128;
    const int M  = gridDim.x * 128;
    const uint32_t* Bp = B2 + (size_t)b * Kp * HW * 2;
    float* Cp = Cdst + (size_t)b * M * HW;

    float c[4][4][4];
#pragma unroll
    for (int mi = 0; mi < 4; mi++)
#pragma unroll
        for (int ni = 0; ni < 4; ni++)
#pragma unroll
            for (int r = 0; r < 4; r++) c[mi][ni][r] = 0.f;

    const int nch = Kp >> 4;

    // A: 1024 16B-chunks (128 rows x 8), B: 1024 (16 rows x 64) -> 8 per thread
    const int ar = tid >> 3, ao = (tid & 7);           // +i*256: rows advance by 32
    const int bkp = tid >> 6, bo = (tid & 63);         // +i*256: kp advances by 4

    auto load_stage = [&](int st, int ck) {
        uint32_t sb = sbase + st * STAGE;
#pragma unroll
        for (int i = 0; i < 4; ++i) {
            int row = ar + i * 32;
            const uint32_t* src = A2 + ((size_t)(m0 + row) * Kp + ck * 16 + ao * 2) * 2;
            CP_ASYNC16(sb + (row * A_STRIDE + ao * 4) * 4, src);
        }
#pragma unroll
        for (int i = 0; i < 4; ++i) {
            int kp = bkp + i * 4;
            const uint32_t* src = Bp + ((size_t)(ck * 16 + kp) * HW + n0 + bo * 2) * 2;
            CP_ASYNC16(sb + ST_B + (kp * B_STRIDE + bo * 4) * 4, src);
        }
        asm volatile("cp.async.commit_group;" ::: "memory");
    };

    load_stage(0, 0);
    load_stage(1, 1);

    int st = 0;
    for (int ck = 0; ck < nch; ++ck) {
        if (ck + 1 < nch) {
            asm volatile("cp.async.wait_group 1;" ::: "memory");
        } else {
            asm volatile("cp.async.wait_group 0;" ::: "memory");
        }
        __syncthreads();
        if (ck + 2 < nch) {
            int st2 = st + 2 >= 3 ? st - 1 : st + 2;
            load_stage(st2, ck + 2);
        }

        const uint2* As2 = (const uint2*)(smem + st * STAGE);           // [m][20]
        const uint2* Bs2 = (const uint2*)(smem + st * STAGE + ST_B);    // [kp][132]

#pragma unroll
        for (int ks = 0; ks < 2; ++ks) {
            const int kb = ks * 8;
            uint32_t bbf[4][2], bsf[4][2];
#pragma unroll
            for (int ni = 0; ni < 4; ++ni) {
                int col = warpN + ni * 8 + lq;
                uint2 v0 = Bs2[(kb + lr) * 132 + col];
                uint2 v1 = Bs2[(kb + lr + 4) * 132 + col];
                bbf[ni][0] = v0.x; bsf[ni][0] = v0.y;
                bbf[ni][1] = v1.x; bsf[ni][1] = v1.y;
            }
#pragma unroll
            for (int mi = 0; mi < 4; ++mi) {
                int r = warpM + mi * 16 + lq;
                int kc = kb + lr;
                uint2 a0 = As2[r * 20 + kc];
                uint2 a1 = As2[(r + 8) * 20 + kc];
                uint2 a2 = As2[r * 20 + kc + 4];
                uint2 a3 = As2[(r + 8) * 20 + kc + 4];
                uint32_t abf[4] = { a0.x, a1.x, a2.x, a3.x };
                uint32_t asf[4] = { a0.y, a1.y, a2.y, a3.y };
#pragma unroll
                for (int ni = 0; ni < 4; ++ni) {
                    MMA_F16(c[mi][ni], asf, bbf[ni]);   // small x big
                    MMA_F16(c[mi][ni], abf, bsf[ni]);   // big x small
                    MMA_F16(c[mi][ni], abf, bbf[ni]);   // big x big
                }
            }
        }
        st = (st + 1 == 3) ? 0 : st + 1;
    }

#pragma unroll
    for (int mi = 0; mi < 4; ++mi) {
        int r0 = m0 + warpM + mi * 16 + lq;
        int r1 = r0 + 8;
        float s0 = INV_SC, b0 = 0.f, s1 = INV_SC, b1 = 0.f;
        if (bn_gamma) {
            float inv0 = bn_gamma[r0] * rsqrtf(bn_var[r0] + 1e-5f);
            float inv1 = bn_gamma[r1] * rsqrtf(bn_var[r1] + 1e-5f);
            s0 = inv0 * INV_SC; b0 = bn_beta[r0] - bn_mean[r0] * inv0;
            s1 = inv1 * INV_SC; b1 = bn_beta[r1] - bn_mean[r1] * inv1;
        }
#pragma unroll
        for (int ni = 0; ni < 4; ++ni) {
            int n = n0 + warpN + ni * 8 + lr * 2;
            float2 v0, v1;
            v0.x = c[mi][ni][0] * s0 + b0;
            v0.y = c[mi][ni][1] * s0 + b0;
            v1.x = c[mi][ni][2] * s1 + b1;
            v1.y = c[mi][ni][3] * s1 + b1;
            *reinterpret_cast<float2*>(&Cp[(size_t)r0 * HW + n]) = v0;
            *reinterpret_cast<float2*>(&Cp[(size_t)r1 * HW + n]) = v1;
        }
    }
}

// ---------------- fused depthwise 5x5 + grouped pointwise 8x8 -> agg ----------------
// R16 version (measured 129us). Do not perturb.
__global__ __launch_bounds__(256, 2)
void dwpw_kernel(const float* __restrict__ qkv,
                 const float* __restrict__ w_dw,
                 const float* __restrict__ w_pw,
                 float* __restrict__ agg)
{
    const int tile = blockIdx.x;
    const int g = blockIdx.y;
    const int b = blockIdx.z;
    const int ty0 = (tile >> 1) * 32;
    const int tx0 = (tile & 1) * 32;

    __shared__ float s_in[8][36][36];
    __shared__ float s_dw[8][25];
    __shared__ float s_pw[8][8];

    const int tid = threadIdx.x;
    if (tid < 200) s_dw[tid / 25][tid % 25] = w_dw[(g * 8 + tid / 25) * 25 + tid % 25];
    if (tid < 64)  s_pw[tid >> 3][tid & 7] = w_pw[g * 64 + tid];

    const float* base = qkv + ((size_t)b * 768 + g * 8) * HW;
    {
        float* s_flat = &s_in[0][0][0];
        const int yoff = ty0 - 2, xoff = tx0 - 2;
        int cc = 0;
        int r = tid / 36;
        int col = tid - r * 36;
        for (int idx = tid; idx < 8 * 36 * 36; idx += 256) {
            int y = yoff + r, x = xoff + col;
            float v = 0.f;
            if ((unsigned)y < 64u && (unsigned)x < 64u)
                v = base[(cc << 12) + (y << 6) + x];
            s_flat[idx] = v;
            col += 4; r += 7;
            if (col >= 36) { col -= 36; r += 1; }
            if (r >= 36)   { r -= 36; cc += 1; }
        }
    }
    __syncthreads();

    const int px  = tid & 31;
    const int py0 = (tid >> 5) * 4;

    float out[8][4];
#pragma unroll
    for (int o = 0; o < 8; ++o)
#pragma unroll
        for (int p = 0; p < 4; ++p) out[o][p] = 0.f;

#pragma unroll
    for (int c = 0; c < 8; ++c) {
        float w[25];
#pragma unroll
        for (int i = 0; i < 25; ++i) w[i] = s_dw[c][i];

        float acc[4] = {0.f, 0.f, 0.f, 0.f};
#pragma unroll
        for (int j = 0; j < 8; ++j) {
            float win[5];
#pragma unroll
            for (int dx = 0; dx < 5; ++dx) win[dx] = s_in[c][py0 + j][px + dx];
#pragma unroll
            for (int o = 0; o < 4; ++o) {
                const int dy = j - o;
                if (dy >= 0 && dy <= 4) {
#pragma unroll
                    for (int dx = 0; dx < 5; ++dx)
                        acc[o] = fmaf(win[dx], w[dy * 5 + dx], acc[o]);
                }
            }
        }
#pragma unroll
        for (int o = 0; o < 8; ++o) {
            float pw = s_pw[o][c];
#pragma unroll
            for (int p = 0; p < 4; ++p) out[o][p] = fmaf(pw, acc[p], out[o][p]);
        }
    }

    float* obase = agg + ((size_t)b * 768 + g * 8) * HW;
#pragma unroll
    for (int o = 0; o < 8; ++o) {
#pragma unroll
        for (int p = 0; p < 4; ++p) {
            int off = (ty0 + py0 + p) * 64 + (tx0 + px);
            obase[(size_t)o * HW + off] = out[o][p];
        }
    }
}

// ---------------- kv = sum_p relu(k)_d * [v_e | 1]  per (b, head) ----------------
__global__ __launch_bounds__(256, 4)
void kv_kernel(const float* __restrict__ qkv,
               const float* __restrict__ agg,
               float* __restrict__ kvout)
{
    const int h = blockIdx.x, b = blockIdx.y;
    const float* src = (h < 32) ? qkv : agg;
    const int cbase = (h & 31) * 24;
    const float* kp = src + ((size_t)b * 768 + cbase + 8) * HW;
    const float* vp = src + ((size_t)b * 768 + cbase + 16) * HW;

    float acc[8][9];
#pragma unroll
    for (int d = 0; d < 8; d++)
#pragma unroll
        for (int e = 0; e < 9; e++) acc[d][e] = 0.f;

    for (int p = threadIdx.x; p < HW; p += 256) {
        float kk[8], vv[8];
#pragma unroll
        for (int d = 0; d < 8; d++) kk[d] = fmaxf(kp[(size_t)d * HW + p], 0.f);
#pragma unroll
        for (int e = 0; e < 8; e++) vv[e] = vp[(size_t)e * HW + p];
#pragma unroll
        for (int d = 0; d < 8; d++) {
#pragma unroll
            for (int e = 0; e < 8; e++) acc[d][e] = fmaf(kk[d], vv[e], acc[d][e]);
            acc[d][8] += kk[d];
        }
    }

    __shared__ float red[8][72];
    const int lane = threadIdx.x & 31, w = threadIdx.x >> 5;
#pragma unroll
    for (int i = 0; i < 72; ++i) {
        float v = acc[i / 9][i % 9];
#pragma unroll
        for (int off = 16; off; off >>= 1) v += __shfl_down_sync(0xffffffffu, v, off);
        if (lane == 0) red[w][i] = v;
    }
    __syncthreads();
    if (threadIdx.x < 72) {
        float s = 0.f;
#pragma unroll
        for (int w2 = 0; w2 < 8; ++w2) s += red[w2][threadIdx.x];
        kvout[((size_t)b * 64 + h) * 72 + threadIdx.x] = s;
    }
}

// ---------------- apply + fused att split (interleaved pairs), 4 px/thread ----------------
__global__ __launch_bounds__(256, 4)
void apply_kernel(const float* __restrict__ qkv,
                  const float* __restrict__ agg,
                  const float* __restrict__ kvin,
                  uint32_t* __restrict__ att2)
{
    const int h = blockIdx.y, b = blockIdx.z;
    __shared__ float kv[8][9];
    if (threadIdx.x < 72)
        kv[threadIdx.x / 9][threadIdx.x % 9] = kvin[((size_t)b * 64 + h) * 72 + threadIdx.x];
    __syncthreads();

    const float* src = (h < 32) ? qkv : agg;
    const int cbase = (h & 31) * 24;
    const float* qp = src + ((size_t)b * 768 + cbase) * HW;
    const int p = (blockIdx.x * 256 + threadIdx.x) * 4;

    float4 q[8];
#pragma unroll
    for (int d = 0; d < 8; d++) {
        float4 v = *reinterpret_cast<const float4*>(&qp[(size_t)d * HW + p]);
        v.x = fmaxf(v.x, 0.f); v.y = fmaxf(v.y, 0.f);
        v.z = fmaxf(v.z, 0.f); v.w = fmaxf(v.w, 0.f);
        q[d] = v;
    }

    float4 den = make_float4(0.f, 0.f, 0.f, 0.f);
#pragma unroll
    for (int d = 0; d < 8; d++) {
        float kd = kv[d][8];
        den.x = fmaf(q[d].x, kd, den.x);
        den.y = fmaf(q[d].y, kd, den.y);
        den.z = fmaf(q[d].z, kd, den.z);
        den.w = fmaf(q[d].w, kd, den.w);
    }
    float4 inv;
    inv.x = 1.f / (den.x + 1e-15f);
    inv.y = 1.f / (den.y + 1e-15f);
    inv.z = 1.f / (den.z + 1e-15f);
    inv.w = 1.f / (den.w + 1e-15f);

    float o[8][4];
#pragma unroll
    for (int n = 0; n < 8; ++n) {
        float4 s = make_float4(0.f, 0.f, 0.f, 0.f);
#pragma unroll
        for (int d = 0; d < 8; d++) {
            float kn = kv[d][n];
            s.x = fmaf(q[d].x, kn, s.x);
            s.y = fmaf(q[d].y, kn, s.y);
            s.z = fmaf(q[d].z, kn, s.z);
            s.w = fmaf(q[d].w, kn, s.w);
        }
        o[n][0] = s.x * inv.x; o[n][1] = s.y * inv.y;
        o[n][2] = s.z * inv.z; o[n][3] = s.w * inv.w;
    }

    // write interleaved (big, small) pairs: [b][kp][px][2]
#pragma unroll
    for (int j = 0; j < 4; ++j) {
        uint32_t vb[4], vs[4];
        splith(o[2 * j][0], o[2 * j + 1][0], B_SCALE, vb[0], vs[0]);
        splith(o[2 * j][1], o[2 * j + 1][1], B_SCALE, vb[1], vs[1]);
        splith(o[2 * j][2], o[2 * j + 1][2], B_SCALE, vb[2], vs[2]);
        splith(o[2 * j][3], o[2 * j + 1][3], B_SCALE, vb[3], vs[3]);
        uint32_t* wp = att2 + (((size_t)b * 256 + h * 4 + j) * HW + p) * 2;
        *reinterpret_cast<uint4*>(wp)     = make_uint4(vb[0], vs[0], vb[1], vs[1]);
        *reinterpret_cast<uint4*>(wp + 4) = make_uint4(vb[2], vs[2], vb[3], vs[3]);
    }
}

// ---------------- launch ----------------
extern "C" void kernel_launch(void* const* d_in, const int* in_sizes, int n_in,
                              void* d_out, int out_size)
{
    const float* x        = (const float*)d_in[0];
    const float* w_qkv    = (const float*)d_in[1];
    const float* w_dw     = (const float*)d_in[2];
    const float* w_pw     = (const float*)d_in[3];
    const float* w_proj   = (const float*)d_in[4];
    const float* bn_gamma = (const float*)d_in[5];
    const float* bn_beta  = (const float*)d_in[6];
    const float* bn_mean  = (const float*)d_in[7];
    const float* bn_var   = (const float*)d_in[8];
    float* out = (float*)d_out;

    float *qkv, *agg, *kv;
    uint32_t *x2, *att2, *wq2, *wp2;
    cudaGetSymbolAddress((void**)&qkv,  g_qkv);
    cudaGetSymbolAddress((void**)&agg,  g_agg);
    cudaGetSymbolAddress((void**)&kv,   g_kv);
    cudaGetSymbolAddress((void**)&x2,   g_x2);
    cudaGetSymbolAddress((void**)&att2, g_att2);
    cudaGetSymbolAddress((void**)&wq2,  g_wq2);
    cudaGetSymbolAddress((void**)&wp2,  g_wp2);

    cudaFuncSetAttribute(gemm_kernel,
                         cudaFuncAttributeMaxDynamicSharedMemorySize, GEMM_SMEM);

    // 0) pre-split weights and x into interleaved fp16 big/small pairs
    split_w_kernel<<<(768 * 128 + 256 * 256 + 255) / 256, 256>>>(w_qkv, w_proj);
    split_x_kernel<<<(8 * 128 * 4096) / 256, 256>>>(x);

    // 1) qkv = w_qkv @ x   (M=768, Kp=128)
    gemm_kernel<<<dim3(6, HW / 128, NB), 256, GEMM_SMEM>>>(
        wq2, x2, qkv, 128, nullptr, nullptr, nullptr, nullptr);

    // 2) agg = grouped-pw(depthwise5x5(qkv))
    dwpw_kernel<<<dim3(4, 96, NB), 256>>>(qkv, w_dw, w_pw, agg);

    // 3) kv reduction per (b, head)
    kv_kernel<<<dim3(64, NB), 256>>>(qkv, agg, kv);

    // 4) apply -> att (interleaved fp16 split), 4 px/thread
    apply_kernel<<<dim3(HW / 1024, 64, NB), 256>>>(qkv, agg, kv, att2);

    // 5) out = BN(w_proj @ att)   (M=256, Kp=256)
    gemm_kernel<<<dim3(2, HW / 128, NB), 256, GEMM_SMEM>>>(
        wp2, att2, out, 256, bn_gamma, bn_beta, bn_mean, bn_var);
}